// round 11
// baseline (speedup 1.0000x reference)
#include <cuda_runtime.h>

#define EPS 1e-8f
#define B_SZ 8192
#define D_SZ 4096

// Scratch. Zero-initialized at module load; k_final restores zeros each replay.
__device__ float g_msum[D_SZ];
__device__ float g_n0;           // count of label-0 rows
__device__ float g_sq0, g_sq1;   // unscaled loss accumulators

__device__ __forceinline__ float warpReduce(float v) {
    #pragma unroll
    for (int o = 16; o > 0; o >>= 1) v += __shfl_down_sync(0xffffffffu, v, o);
    return v;
}

__device__ __forceinline__ float mask0_of(const float* __restrict__ labels, int row) {
    // jnp.argmax over C=2: label 1 only if labels[1] > labels[0]
    return (labels[2 * row + 1] > labels[2 * row]) ? 0.f : 1.f;
}

// Pass 1: masked column sums. No barriers.
// Grid: 4 column tiles (1024 floats each) x 256 row groups (32 rows) = 1024 blocks.
#define ROWS1 32
__global__ void __launch_bounds__(256) k_pass1(const float* __restrict__ datas,
                                               const float* __restrict__ labels) {
    const int tid     = threadIdx.x;
    const int colTile = blockIdx.x & 3;
    const int rowGrp  = blockIdx.x >> 2;
    const int col4    = colTile * 256 + tid;       // float4 column index
    const int row0    = rowGrp * ROWS1;

    // colTile-0 blocks also accumulate n0 for their 32 rows (warp 0).
    const int wid = tid >> 5, lane = tid & 31;
    if (colTile == 0 && wid == 0) {
        float m = mask0_of(labels, row0 + lane);
        m = warpReduce(m);
        if (lane == 0) atomicAdd(&g_n0, m);
    }

    const float4* base = reinterpret_cast<const float4*>(datas) + col4;

    float4 a0 = {0,0,0,0}, a1 = {0,0,0,0}, a2 = {0,0,0,0}, a3 = {0,0,0,0};
    #pragma unroll 4
    for (int r = 0; r < ROWS1; r += 4) {
        const float m0 = mask0_of(labels, row0 + r + 0);
        const float m1 = mask0_of(labels, row0 + r + 1);
        const float m2 = mask0_of(labels, row0 + r + 2);
        const float m3 = mask0_of(labels, row0 + r + 3);
        float4 v0 = base[(size_t)(row0 + r + 0) * (D_SZ / 4)];
        float4 v1 = base[(size_t)(row0 + r + 1) * (D_SZ / 4)];
        float4 v2 = base[(size_t)(row0 + r + 2) * (D_SZ / 4)];
        float4 v3 = base[(size_t)(row0 + r + 3) * (D_SZ / 4)];
        a0.x += m0 * v0.x; a0.y += m0 * v0.y; a0.z += m0 * v0.z; a0.w += m0 * v0.w;
        a1.x += m1 * v1.x; a1.y += m1 * v1.y; a1.z += m1 * v1.z; a1.w += m1 * v1.w;
        a2.x += m2 * v2.x; a2.y += m2 * v2.y; a2.z += m2 * v2.z; a2.w += m2 * v2.w;
        a3.x += m3 * v3.x; a3.y += m3 * v3.y; a3.z += m3 * v3.z; a3.w += m3 * v3.w;
    }
    atomicAdd(&g_msum[4 * col4 + 0], (a0.x + a1.x) + (a2.x + a3.x));
    atomicAdd(&g_msum[4 * col4 + 1], (a0.y + a1.y) + (a2.y + a3.y));
    atomicAdd(&g_msum[4 * col4 + 2], (a0.z + a1.z) + (a2.z + a3.z));
    atomicAdd(&g_msum[4 * col4 + 3], (a0.w + a1.w) + (a2.w + a3.w));
}

// Pass 2: 2 rows per warp, conflict-free smem indexing (16B lane stride).
// Accumulates the UNSCALED quantities
//   Sq0 = sum_{label0} |d.msum| / ||d||,  Sq1 = sum_{label1} |d.msum| / ||d||.
// 512 blocks x 8 warps x 2 rows = 8192 rows.  (Byte-identical to R8.)
__global__ void __launch_bounds__(256) k_pass2(const float* __restrict__ datas,
                                               const float* __restrict__ labels) {
    const int tid  = threadIdx.x;
    const int lane = tid & 31, wid = tid >> 5;
    __shared__ float4 sm4[D_SZ / 4];
    __shared__ float s0[8], s1[8];
    {
        const float4* gm4 = reinterpret_cast<const float4*>(g_msum);
        for (int i = tid; i < D_SZ / 4; i += 256) sm4[i] = gm4[i];
    }
    __syncthreads();

    const int r0 = blockIdx.x * 16 + wid * 2;
    const int r1 = r0 + 1;
    const float4* p0 = reinterpret_cast<const float4*>(datas + (size_t)r0 * D_SZ);
    const float4* p1 = reinterpret_cast<const float4*>(datas + (size_t)r1 * D_SZ);

    float dot0 = 0.f, ss0 = 0.f, dot1 = 0.f, ss1 = 0.f;
    #pragma unroll 4
    for (int i = 0; i < D_SZ / 4 / 64; i++) {          // 16 iterations
        const int ia = lane + 64 * i;                   // consecutive chunk A
        const int ib = ia + 32;                         // consecutive chunk B
        float4 v0a = p0[ia], v0b = p0[ib];
        float4 v1a = p1[ia], v1b = p1[ib];
        float4 wa = sm4[ia], wb = sm4[ib];
        dot0 += v0a.x * wa.x + v0a.y * wa.y + v0a.z * wa.z + v0a.w * wa.w
              + v0b.x * wb.x + v0b.y * wb.y + v0b.z * wb.z + v0b.w * wb.w;
        ss0  += v0a.x * v0a.x + v0a.y * v0a.y + v0a.z * v0a.z + v0a.w * v0a.w
              + v0b.x * v0b.x + v0b.y * v0b.y + v0b.z * v0b.z + v0b.w * v0b.w;
        dot1 += v1a.x * wa.x + v1a.y * wa.y + v1a.z * wa.z + v1a.w * wa.w
              + v1b.x * wb.x + v1b.y * wb.y + v1b.z * wb.z + v1b.w * wb.w;
        ss1  += v1a.x * v1a.x + v1a.y * v1a.y + v1a.z * v1a.z + v1a.w * v1a.w
              + v1b.x * v1b.x + v1b.y * v1b.y + v1b.z * v1b.z + v1b.w * v1b.w;
    }
    dot0 = warpReduce(dot0);
    ss0  = warpReduce(ss0);
    dot1 = warpReduce(dot1);
    ss1  = warpReduce(ss1);

    if (lane == 0) {
        float q0 = fabsf(dot0) / fmaxf(sqrtf(ss0), EPS);
        float q1 = fabsf(dot1) / fmaxf(sqrtf(ss1), EPS);
        float m0 = mask0_of(labels, r0);
        float m1 = mask0_of(labels, r1);
        s0[wid] = m0 * q0 + m1 * q1;
        s1[wid] = (1.f - m0) * q0 + (1.f - m1) * q1;
    }
    __syncthreads();
    if (tid == 0) {
        float a = 0.f, b = 0.f;
        #pragma unroll
        for (int i = 0; i < 8; i++) { a += s0[i]; b += s1[i]; }
        atomicAdd(&g_sq0, a);
        atomicAdd(&g_sq1, b);
    }
}

// Finalize (single block): reduce ||msum||^2, apply the factored-out cosine
// scale, write outputs with edge-case guards, restore scratch to zero.
__global__ void __launch_bounds__(256) k_final(float* __restrict__ out) {
    const int tid = threadIdx.x;
    const int lane = tid & 31, wid = tid >> 5;
    float msq = 0.f;
    float mv[D_SZ / 256];
    #pragma unroll
    for (int i = 0; i < D_SZ / 256; i++) {
        mv[i] = g_msum[tid + i * 256];
        msq += mv[i] * mv[i];
    }
    msq = warpReduce(msq);
    __shared__ float sb[8];
    if (lane == 0) sb[wid] = msq;
    __syncthreads();
    if (tid == 0) {
        float b = 0.f;
        #pragma unroll
        for (int i = 0; i < 8; i++) b += sb[i];
        float a = g_n0;
        float n1 = (float)B_SZ - a;
        float n0max = fmaxf(a, 1.f);
        float n1max = fmaxf(n1, 1.f);
        // mean_vec = msum/n0max; m_norm = max(||msum||/n0max, EPS)
        float mnorm = fmaxf(sqrtf(b) / n0max, EPS);
        float scale = 1.f / (n0max * mnorm);     // ac_i = scale * |dot_i| / xn_i
        float sim = (a > 0.f) ? (a - scale * g_sq0) / n0max : 0.f;
        float dif = (a > 0.f && n1 > 0.f) ? (scale * g_sq1) / n1max : 0.f;
        out[0] = sim + dif;  // total_loss
        out[1] = sim;        // sim_loss
        out[2] = dif;        // differ_loss
        g_sq0 = 0.f;
        g_sq1 = 0.f;
        g_n0  = 0.f;
    }
    // Re-zero msum for the next replay.
    #pragma unroll
    for (int i = 0; i < D_SZ / 256; i++) g_msum[tid + i * 256] = 0.f;
}

extern "C" void kernel_launch(void* const* d_in, const int* in_sizes, int n_in,
                              void* d_out, int out_size) {
    // Identify labels (smaller tensor) vs datas by size.
    const float* labels = (const float*)d_in[0];
    const float* datas  = (const float*)d_in[1];
    if (n_in >= 2 && in_sizes[0] > in_sizes[1]) {
        labels = (const float*)d_in[1];
        datas  = (const float*)d_in[0];
    }

    k_pass1<<<4 * (B_SZ / ROWS1), 256>>>(datas, labels);   // 1024 blocks
    k_pass2<<<B_SZ / 16, 256>>>(datas, labels);            // 512 blocks
    k_final<<<1, 256>>>((float*)d_out);
}

// round 17
// speedup vs baseline: 1.1854x; 1.1854x over previous
#include <cuda_runtime.h>

#define EPS 1e-8f
#define B_SZ 8192
#define D_SZ 4096

// Scratch. Zero-initialized at module load; k_final restores zeros each replay.
__device__ float g_msum[D_SZ];
__device__ float g_n0;           // count of label-0 rows
__device__ float g_sq0, g_sq1;   // unscaled loss accumulators

__device__ __forceinline__ float warpReduce(float v) {
    #pragma unroll
    for (int o = 16; o > 0; o >>= 1) v += __shfl_down_sync(0xffffffffu, v, o);
    return v;
}

__device__ __forceinline__ float mask0_of(const float* __restrict__ labels, int row) {
    // argmax over C=2: label 1 only if labels[1] > labels[0]
    return (labels[2 * row + 1] > labels[2 * row]) ? 0.f : 1.f;
}

// Pass 1: masked column sums. No barriers. R8 decomposition (512 blocks),
// but 8 rows in flight per loop iteration (double the per-thread MLP).
// Grid: 4 column tiles (1024 floats each) x 128 row groups (64 rows) = 512 blocks.
#define ROWS1 64
__global__ void __launch_bounds__(256) k_pass1(const float* __restrict__ datas,
                                               const float* __restrict__ labels) {
    const int tid     = threadIdx.x;
    const int colTile = blockIdx.x & 3;
    const int rowGrp  = blockIdx.x >> 2;
    const int col4    = colTile * 256 + tid;       // float4 column index
    const int row0    = rowGrp * ROWS1;

    // colTile-0 blocks also accumulate n0 for their 64 rows (warps 0-1).
    const int wid = tid >> 5, lane = tid & 31;
    if (colTile == 0 && wid < 2) {
        float m = mask0_of(labels, row0 + tid);
        m = warpReduce(m);
        if (lane == 0) atomicAdd(&g_n0, m);
    }

    const float4* base = reinterpret_cast<const float4*>(datas) + col4;

    float4 a0 = {0,0,0,0}, a1 = {0,0,0,0}, a2 = {0,0,0,0}, a3 = {0,0,0,0};
    #pragma unroll 2
    for (int r = 0; r < ROWS1; r += 8) {
        const float m0 = mask0_of(labels, row0 + r + 0);
        const float m1 = mask0_of(labels, row0 + r + 1);
        const float m2 = mask0_of(labels, row0 + r + 2);
        const float m3 = mask0_of(labels, row0 + r + 3);
        const float m4 = mask0_of(labels, row0 + r + 4);
        const float m5 = mask0_of(labels, row0 + r + 5);
        const float m6 = mask0_of(labels, row0 + r + 6);
        const float m7 = mask0_of(labels, row0 + r + 7);
        float4 v0 = base[(size_t)(row0 + r + 0) * (D_SZ / 4)];
        float4 v1 = base[(size_t)(row0 + r + 1) * (D_SZ / 4)];
        float4 v2 = base[(size_t)(row0 + r + 2) * (D_SZ / 4)];
        float4 v3 = base[(size_t)(row0 + r + 3) * (D_SZ / 4)];
        float4 v4 = base[(size_t)(row0 + r + 4) * (D_SZ / 4)];
        float4 v5 = base[(size_t)(row0 + r + 5) * (D_SZ / 4)];
        float4 v6 = base[(size_t)(row0 + r + 6) * (D_SZ / 4)];
        float4 v7 = base[(size_t)(row0 + r + 7) * (D_SZ / 4)];
        a0.x += m0 * v0.x; a0.y += m0 * v0.y; a0.z += m0 * v0.z; a0.w += m0 * v0.w;
        a1.x += m1 * v1.x; a1.y += m1 * v1.y; a1.z += m1 * v1.z; a1.w += m1 * v1.w;
        a2.x += m2 * v2.x; a2.y += m2 * v2.y; a2.z += m2 * v2.z; a2.w += m2 * v2.w;
        a3.x += m3 * v3.x; a3.y += m3 * v3.y; a3.z += m3 * v3.z; a3.w += m3 * v3.w;
        a0.x += m4 * v4.x; a0.y += m4 * v4.y; a0.z += m4 * v4.z; a0.w += m4 * v4.w;
        a1.x += m5 * v5.x; a1.y += m5 * v5.y; a1.z += m5 * v5.z; a1.w += m5 * v5.w;
        a2.x += m6 * v6.x; a2.y += m6 * v6.y; a2.z += m6 * v6.z; a2.w += m6 * v6.w;
        a3.x += m7 * v7.x; a3.y += m7 * v7.y; a3.z += m7 * v7.z; a3.w += m7 * v7.w;
    }
    atomicAdd(&g_msum[4 * col4 + 0], (a0.x + a1.x) + (a2.x + a3.x));
    atomicAdd(&g_msum[4 * col4 + 1], (a0.y + a1.y) + (a2.y + a3.y));
    atomicAdd(&g_msum[4 * col4 + 2], (a0.z + a1.z) + (a2.z + a3.z));
    atomicAdd(&g_msum[4 * col4 + 3], (a0.w + a1.w) + (a2.w + a3.w));
}

// Pass 2: 2 rows per warp, conflict-free smem indexing (16B lane stride).
// Accumulates the UNSCALED quantities
//   Sq0 = sum_{label0} |d.msum| / ||d||,  Sq1 = sum_{label1} |d.msum| / ||d||.
// 512 blocks x 8 warps x 2 rows = 8192 rows.  (Byte-identical to R8.)
__global__ void __launch_bounds__(256) k_pass2(const float* __restrict__ datas,
                                               const float* __restrict__ labels) {
    const int tid  = threadIdx.x;
    const int lane = tid & 31, wid = tid >> 5;
    __shared__ float4 sm4[D_SZ / 4];
    __shared__ float s0[8], s1[8];
    {
        const float4* gm4 = reinterpret_cast<const float4*>(g_msum);
        for (int i = tid; i < D_SZ / 4; i += 256) sm4[i] = gm4[i];
    }
    __syncthreads();

    const int r0 = blockIdx.x * 16 + wid * 2;
    const int r1 = r0 + 1;
    const float4* p0 = reinterpret_cast<const float4*>(datas + (size_t)r0 * D_SZ);
    const float4* p1 = reinterpret_cast<const float4*>(datas + (size_t)r1 * D_SZ);

    float dot0 = 0.f, ss0 = 0.f, dot1 = 0.f, ss1 = 0.f;
    #pragma unroll 4
    for (int i = 0; i < D_SZ / 4 / 64; i++) {          // 16 iterations
        const int ia = lane + 64 * i;                   // consecutive chunk A
        const int ib = ia + 32;                         // consecutive chunk B
        float4 v0a = p0[ia], v0b = p0[ib];
        float4 v1a = p1[ia], v1b = p1[ib];
        float4 wa = sm4[ia], wb = sm4[ib];
        dot0 += v0a.x * wa.x + v0a.y * wa.y + v0a.z * wa.z + v0a.w * wa.w
              + v0b.x * wb.x + v0b.y * wb.y + v0b.z * wb.z + v0b.w * wb.w;
        ss0  += v0a.x * v0a.x + v0a.y * v0a.y + v0a.z * v0a.z + v0a.w * v0a.w
              + v0b.x * v0b.x + v0b.y * v0b.y + v0b.z * v0b.z + v0b.w * v0b.w;
        dot1 += v1a.x * wa.x + v1a.y * wa.y + v1a.z * wa.z + v1a.w * wa.w
              + v1b.x * wb.x + v1b.y * wb.y + v1b.z * wb.z + v1b.w * wb.w;
        ss1  += v1a.x * v1a.x + v1a.y * v1a.y + v1a.z * v1a.z + v1a.w * v1a.w
              + v1b.x * v1b.x + v1b.y * v1b.y + v1b.z * v1b.z + v1b.w * v1b.w;
    }
    dot0 = warpReduce(dot0);
    ss0  = warpReduce(ss0);
    dot1 = warpReduce(dot1);
    ss1  = warpReduce(ss1);

    if (lane == 0) {
        float q0 = fabsf(dot0) / fmaxf(sqrtf(ss0), EPS);
        float q1 = fabsf(dot1) / fmaxf(sqrtf(ss1), EPS);
        float m0 = mask0_of(labels, r0);
        float m1 = mask0_of(labels, r1);
        s0[wid] = m0 * q0 + m1 * q1;
        s1[wid] = (1.f - m0) * q0 + (1.f - m1) * q1;
    }
    __syncthreads();
    if (tid == 0) {
        float a = 0.f, b = 0.f;
        #pragma unroll
        for (int i = 0; i < 8; i++) { a += s0[i]; b += s1[i]; }
        atomicAdd(&g_sq0, a);
        atomicAdd(&g_sq1, b);
    }
}

// Finalize (single block): reduce ||msum||^2, apply the factored-out cosine
// scale, write outputs with edge-case guards, restore scratch to zero.
__global__ void __launch_bounds__(256) k_final(float* __restrict__ out) {
    const int tid = threadIdx.x;
    const int lane = tid & 31, wid = tid >> 5;
    float msq = 0.f;
    float mv[D_SZ / 256];
    #pragma unroll
    for (int i = 0; i < D_SZ / 256; i++) {
        mv[i] = g_msum[tid + i * 256];
        msq += mv[i] * mv[i];
    }
    msq = warpReduce(msq);
    __shared__ float sb[8];
    if (lane == 0) sb[wid] = msq;
    __syncthreads();
    if (tid == 0) {
        float b = 0.f;
        #pragma unroll
        for (int i = 0; i < 8; i++) b += sb[i];
        float a = g_n0;
        float n1 = (float)B_SZ - a;
        float n0max = fmaxf(a, 1.f);
        float n1max = fmaxf(n1, 1.f);
        // mean_vec = msum/n0max; m_norm = max(||msum||/n0max, EPS)
        float mnorm = fmaxf(sqrtf(b) / n0max, EPS);
        float scale = 1.f / (n0max * mnorm);     // ac_i = scale * |dot_i| / xn_i
        float sim = (a > 0.f) ? (a - scale * g_sq0) / n0max : 0.f;
        float dif = (a > 0.f && n1 > 0.f) ? (scale * g_sq1) / n1max : 0.f;
        out[0] = sim + dif;  // total_loss
        out[1] = sim;        // sim_loss
        out[2] = dif;        // differ_loss
        g_sq0 = 0.f;
        g_sq1 = 0.f;
        g_n0  = 0.f;
    }
    // Re-zero msum for the next replay.
    #pragma unroll
    for (int i = 0; i < D_SZ / 256; i++) g_msum[tid + i * 256] = 0.f;
}

extern "C" void kernel_launch(void* const* d_in, const int* in_sizes, int n_in,
                              void* d_out, int out_size) {
    // Identify labels (smaller tensor) vs datas by size.
    const float* labels = (const float*)d_in[0];
    const float* datas  = (const float*)d_in[1];
    if (n_in >= 2 && in_sizes[0] > in_sizes[1]) {
        labels = (const float*)d_in[1];
        datas  = (const float*)d_in[0];
    }

    k_pass1<<<4 * (B_SZ / ROWS1), 256>>>(datas, labels);   // 512 blocks
    k_pass2<<<B_SZ / 16, 256>>>(datas, labels);            // 512 blocks
    k_final<<<1, 256>>>((float*)d_out);
}